// round 1
// baseline (speedup 1.0000x reference)
#include <cuda_runtime.h>
#include <math.h>

#define EMB   1024
#define HEADS 16
#define HDIM  64
#define BATCH 16
#define SEQ   1024
#define NTOK  (BATCH*SEQ)

// Scratch (allocation is forbidden; __device__ globals are the sanctioned path)
__device__ float g_q[(size_t)NTOK * EMB];    // [B,H,P,D]
__device__ float g_k[(size_t)NTOK * EMB];    // [B,H,P,D]
__device__ float g_v[(size_t)NTOK * EMB];    // [B,H,P,D]
__device__ float g_ctx[(size_t)NTOK * EMB];  // [B,P,E]

// ---------------------------------------------------------------------------
// GEMM: C = A @ W^T + bias.  A:[NTOK,EMB] row-major, W:[EMB,EMB] row-major.
// DST: 0 -> g_q (scatter to [B,H,P,D]), 1 -> g_k, 2 -> g_v,
//      3 -> Cout param, plain [NTOK,EMB], with A taken from g_ctx.
// Tiling: 128x128x16, 256 threads, 8x8 per-thread microtile.
// ---------------------------------------------------------------------------
template<int DST>
__global__ void __launch_bounds__(256)
gemm_xwT(const float* __restrict__ Ain, const float* __restrict__ W,
         const float* __restrict__ bias, float* __restrict__ Cout)
{
    __shared__ float As[16][132];   // [k][m], padded pitch 132 (float4-aligned)
    __shared__ float Bs[16][132];   // [k][n]

    const float* A = (DST == 3) ? (const float*)g_ctx : Ain;
    float* C = (DST == 0) ? (float*)g_q
             : (DST == 1) ? (float*)g_k
             : (DST == 2) ? (float*)g_v
             : Cout;

    const int tid = threadIdx.x;
    const int tx = tid & 15;        // 0..15 -> n microtile
    const int ty = tid >> 4;        // 0..15 -> m microtile
    const int mBase = blockIdx.y * 128;
    const int nBase = blockIdx.x * 128;

    const float* Ag = A + (size_t)mBase * EMB;
    const float* Wg = W + (size_t)nBase * EMB;

    float acc[8][8];
    #pragma unroll
    for (int i = 0; i < 8; i++)
        #pragma unroll
        for (int j = 0; j < 8; j++) acc[i][j] = 0.f;

    for (int k0 = 0; k0 < EMB; k0 += 16) {
        // Load 128x16 tiles of A and W, transposed into [k][m] / [k][n].
        #pragma unroll
        for (int r = 0; r < 2; r++) {
            int f   = tid + r * 256;      // 0..511
            int row = f >> 2;             // 0..127
            int kq  = (f & 3) << 2;       // 0,4,8,12
            float4 a4 = *(const float4*)&Ag[(size_t)row * EMB + k0 + kq];
            As[kq+0][row] = a4.x; As[kq+1][row] = a4.y;
            As[kq+2][row] = a4.z; As[kq+3][row] = a4.w;
            float4 b4 = *(const float4*)&Wg[(size_t)row * EMB + k0 + kq];
            Bs[kq+0][row] = b4.x; Bs[kq+1][row] = b4.y;
            Bs[kq+2][row] = b4.z; Bs[kq+3][row] = b4.w;
        }
        __syncthreads();

        #pragma unroll
        for (int k = 0; k < 16; k++) {
            float4 a0 = *(const float4*)&As[k][ty*8];
            float4 a1 = *(const float4*)&As[k][ty*8+4];
            float4 b0 = *(const float4*)&Bs[k][tx*8];
            float4 b1 = *(const float4*)&Bs[k][tx*8+4];
            float av[8] = {a0.x,a0.y,a0.z,a0.w,a1.x,a1.y,a1.z,a1.w};
            float bv[8] = {b0.x,b0.y,b0.z,b0.w,b1.x,b1.y,b1.z,b1.w};
            #pragma unroll
            for (int i = 0; i < 8; i++)
                #pragma unroll
                for (int j = 0; j < 8; j++)
                    acc[i][j] += av[i] * bv[j];
        }
        __syncthreads();
    }

    // Epilogue: bias + store
    const int e0 = nBase + tx * 8;
    float4 bb0 = *(const float4*)&bias[e0];
    float4 bb1 = *(const float4*)&bias[e0 + 4];

    #pragma unroll
    for (int i = 0; i < 8; i++) {
        int n = mBase + ty * 8 + i;
        float4 c0 = make_float4(acc[i][0]+bb0.x, acc[i][1]+bb0.y,
                                acc[i][2]+bb0.z, acc[i][3]+bb0.w);
        float4 c1 = make_float4(acc[i][4]+bb1.x, acc[i][5]+bb1.y,
                                acc[i][6]+bb1.z, acc[i][7]+bb1.w);
        if (DST == 3) {
            float* dst = &C[(size_t)n * EMB + e0];
            *(float4*)dst = c0;
            *(float4*)(dst + 4) = c1;
        } else {
            // scatter to [B,H,P,D]; 8 consecutive e stay inside one head (8|64)
            int b = n >> 10, p = n & 1023;
            int h = e0 >> 6, d = e0 & 63;
            float* dst = &C[(((size_t)(b*HEADS + h) * SEQ) + p) * HDIM + d];
            *(float4*)dst = c0;
            *(float4*)(dst + 4) = c1;
        }
    }
}

// ---------------------------------------------------------------------------
// Flash attention, fp32. One block = one (b,h) x 128 query rows.
// BN=64 keys per iteration, D=64. 256 threads: tx=tid&7 (8 d/key groups),
// ty=tid>>3 (32 row groups of 4 rows). Shuffle reductions across tx lanes.
// ---------------------------------------------------------------------------
#define QS_PITCH 132
#define KS_PITCH 68
#define PS_PITCH 132
#define SMEM_FLOATS (64*QS_PITCH + 64*KS_PITCH + 64*64 + 64*PS_PITCH)

__global__ void __launch_bounds__(256)
attn_flash(float* __restrict__ dummy)
{
    extern __shared__ float sm[];
    float* Qs = sm;                       // [d][m]   64 x 132
    float* Ks = Qs + 64*QS_PITCH;         // [d][n]   64 x 68
    float* Vs = Ks + 64*KS_PITCH;         // [n][d]   64 x 64
    float* Ps = Vs + 64*64;               // [n][m]   64 x 132 (transposed P)

    const int tid = threadIdx.x;
    const int tx = tid & 7;               // 0..7
    const int ty = tid >> 3;              // 0..31
    const int bh = blockIdx.y;            // 0..255
    const int qBase = blockIdx.x * 128;

    const float* Qg = (const float*)g_q + ((size_t)bh * SEQ + qBase) * HDIM;
    const float* Kg = (const float*)g_k + (size_t)bh * SEQ * HDIM;
    const float* Vg = (const float*)g_v + (size_t)bh * SEQ * HDIM;

    const float scale = 0.03125f;  // 1/sqrt(1024)  (ref scales by sqrt(P)!)

    // Load Q tile (128x64), transpose into Qs[d][m]; fold in softmax scale.
    #pragma unroll
    for (int r = 0; r < 8; r++) {
        int f   = tid + r * 256;          // 0..2047
        int row = f >> 4;                 // 0..127
        int dq  = (f & 15) << 2;          // 0..60
        float4 q4 = *(const float4*)&Qg[row * HDIM + dq];
        Qs[(dq+0)*QS_PITCH + row] = q4.x * scale;
        Qs[(dq+1)*QS_PITCH + row] = q4.y * scale;
        Qs[(dq+2)*QS_PITCH + row] = q4.z * scale;
        Qs[(dq+3)*QS_PITCH + row] = q4.w * scale;
    }

    const float NEG_INF = __int_as_float(0xff800000);
    float m[4], l[4], o[4][8];
    #pragma unroll
    for (int i = 0; i < 4; i++) {
        m[i] = NEG_INF; l[i] = 0.f;
        #pragma unroll
        for (int j = 0; j < 8; j++) o[i][j] = 0.f;
    }

    for (int t = 0; t < 16; t++) {
        const float* Kt = Kg + t * 64 * HDIM;
        const float* Vt = Vg + t * 64 * HDIM;
        // Load K (transposed) and V (natural) tiles: 64x64 each.
        #pragma unroll
        for (int r = 0; r < 4; r++) {
            int f   = tid + r * 256;      // 0..1023
            int row = f >> 4;             // 0..63
            int dq  = (f & 15) << 2;      // 0..60
            float4 k4 = *(const float4*)&Kt[row * HDIM + dq];
            Ks[(dq+0)*KS_PITCH + row] = k4.x;
            Ks[(dq+1)*KS_PITCH + row] = k4.y;
            Ks[(dq+2)*KS_PITCH + row] = k4.z;
            Ks[(dq+3)*KS_PITCH + row] = k4.w;
            *(float4*)&Vs[row * 64 + dq] = *(const float4*)&Vt[row * HDIM + dq];
        }
        __syncthreads();

        // S = (Q*scale) @ K^T : each thread 4 rows x 8 keys
        float s[4][8];
        #pragma unroll
        for (int i = 0; i < 4; i++)
            #pragma unroll
            for (int j = 0; j < 8; j++) s[i][j] = 0.f;

        #pragma unroll 8
        for (int d = 0; d < 64; d++) {
            float4 q4 = *(const float4*)&Qs[d*QS_PITCH + ty*4];
            float4 k0 = *(const float4*)&Ks[d*KS_PITCH + tx*8];
            float4 k1 = *(const float4*)&Ks[d*KS_PITCH + tx*8 + 4];
            float qa[4] = {q4.x, q4.y, q4.z, q4.w};
            float kb[8] = {k0.x,k0.y,k0.z,k0.w,k1.x,k1.y,k1.z,k1.w};
            #pragma unroll
            for (int i = 0; i < 4; i++)
                #pragma unroll
                for (int j = 0; j < 8; j++)
                    s[i][j] += qa[i] * kb[j];
        }

        // Online softmax (rows split over tx lanes -> shuffle reduce)
        #pragma unroll
        for (int i = 0; i < 4; i++) {
            float mx = s[i][0];
            #pragma unroll
            for (int j = 1; j < 8; j++) mx = fmaxf(mx, s[i][j]);
            mx = fmaxf(mx, __shfl_xor_sync(0xffffffffu, mx, 1));
            mx = fmaxf(mx, __shfl_xor_sync(0xffffffffu, mx, 2));
            mx = fmaxf(mx, __shfl_xor_sync(0xffffffffu, mx, 4));
            float mnew  = fmaxf(m[i], mx);
            float alpha = __expf(m[i] - mnew);
            float rs = 0.f;
            #pragma unroll
            for (int j = 0; j < 8; j++) {
                float p = __expf(s[i][j] - mnew);
                s[i][j] = p;
                rs += p;
            }
            rs += __shfl_xor_sync(0xffffffffu, rs, 1);
            rs += __shfl_xor_sync(0xffffffffu, rs, 2);
            rs += __shfl_xor_sync(0xffffffffu, rs, 4);
            l[i] = l[i] * alpha + rs;
            m[i] = mnew;
            #pragma unroll
            for (int j = 0; j < 8; j++) o[i][j] *= alpha;
        }

        // Store P transposed: Ps[key][row]
        #pragma unroll
        for (int j = 0; j < 8; j++) {
            *(float4*)&Ps[(tx*8 + j)*PS_PITCH + ty*4] =
                make_float4(s[0][j], s[1][j], s[2][j], s[3][j]);
        }
        __syncthreads();

        // O += P @ V : each thread 4 rows x 8 d-cols
        #pragma unroll 8
        for (int kk = 0; kk < 64; kk++) {
            float4 p4 = *(const float4*)&Ps[kk*PS_PITCH + ty*4];
            float4 v0 = *(const float4*)&Vs[kk*64 + tx*8];
            float4 v1 = *(const float4*)&Vs[kk*64 + tx*8 + 4];
            float pa[4] = {p4.x, p4.y, p4.z, p4.w};
            float vb[8] = {v0.x,v0.y,v0.z,v0.w,v1.x,v1.y,v1.z,v1.w};
            #pragma unroll
            for (int i = 0; i < 4; i++)
                #pragma unroll
                for (int j = 0; j < 8; j++)
                    o[i][j] += pa[i] * vb[j];
        }
        __syncthreads();
    }

    // Normalize and write ctx in [B,P,E] layout
    const int b = bh >> 4, h = bh & 15;
    #pragma unroll
    for (int i = 0; i < 4; i++) {
        float inv = 1.f / l[i];
        int p = qBase + ty * 4 + i;
        float* dst = &g_ctx[((size_t)(b * SEQ + p)) * EMB + h * HDIM + tx * 8];
        *(float4*)dst = make_float4(o[i][0]*inv, o[i][1]*inv,
                                    o[i][2]*inv, o[i][3]*inv);
        *(float4*)(dst + 4) = make_float4(o[i][4]*inv, o[i][5]*inv,
                                          o[i][6]*inv, o[i][7]*inv);
    }
    (void)dummy;
}

// ---------------------------------------------------------------------------
extern "C" void kernel_launch(void* const* d_in, const int* in_sizes, int n_in,
                              void* d_out, int out_size)
{
    const float* x  = (const float*)d_in[0];
    const float* wq = (const float*)d_in[1];
    const float* bq = (const float*)d_in[2];
    const float* wk = (const float*)d_in[3];
    const float* bk = (const float*)d_in[4];
    const float* wv = (const float*)d_in[5];
    const float* bv = (const float*)d_in[6];
    const float* wo = (const float*)d_in[7];
    const float* bo = (const float*)d_in[8];
    float* out = (float*)d_out;

    dim3 ggrid(EMB / 128, NTOK / 128);

    gemm_xwT<0><<<ggrid, 256>>>(x, wq, bq, nullptr);
    gemm_xwT<1><<<ggrid, 256>>>(x, wk, bk, nullptr);
    gemm_xwT<2><<<ggrid, 256>>>(x, wv, bv, nullptr);

    int smem_bytes = SMEM_FLOATS * (int)sizeof(float);
    cudaFuncSetAttribute(attn_flash,
                         cudaFuncAttributeMaxDynamicSharedMemorySize, smem_bytes);
    attn_flash<<<dim3(SEQ / 128, BATCH * HEADS), 256, smem_bytes>>>(nullptr);

    gemm_xwT<3><<<ggrid, 256>>>(nullptr, wo, bo, out);

    (void)in_sizes; (void)n_in; (void)out_size;
}

// round 3
// speedup vs baseline: 3.4724x; 3.4724x over previous
#include <cuda_runtime.h>
#include <math.h>

#define EMB   1024
#define HEADS 16
#define HDIM  64
#define BATCH 16
#define SEQ   1024
#define NTOK  (BATCH*SEQ)

// ---------------- scratch (__device__ globals; allocation is forbidden) ----
__device__ float g_xr[(size_t)NTOK * EMB];        // x rounded to tf32
__device__ float g_wr[4][(size_t)EMB * EMB];      // wq,wk,wv,wo rounded
__device__ float g_q[(size_t)NTOK * EMB];         // [B,H,P,D] tf32 (pre-scaled)
__device__ float g_k[(size_t)NTOK * EMB];         // [B,H,P,D] tf32
__device__ float g_v[(size_t)NTOK * EMB];         // [B,H,P,D] tf32
__device__ float g_ctx[(size_t)NTOK * EMB];       // [B,P,E]  tf32

// ---------------- helpers --------------------------------------------------
__device__ __forceinline__ unsigned f2tf(float f) {
    unsigned u; asm("cvt.rna.tf32.f32 %0, %1;" : "=r"(u) : "f"(f)); return u;
}
__device__ __forceinline__ float rtf(float f) { return __uint_as_float(f2tf(f)); }

__device__ __forceinline__ void mma8(float* c, const unsigned* a, const unsigned* b) {
    asm volatile(
        "mma.sync.aligned.m16n8k8.row.col.f32.tf32.tf32.f32 "
        "{%0,%1,%2,%3},{%4,%5,%6,%7},{%8,%9},{%0,%1,%2,%3};"
        : "+f"(c[0]), "+f"(c[1]), "+f"(c[2]), "+f"(c[3])
        : "r"(a[0]), "r"(a[1]), "r"(a[2]), "r"(a[3]), "r"(b[0]), "r"(b[1]));
}
__device__ __forceinline__ void cpa16(float* s, const float* g) {
    unsigned a = (unsigned)__cvta_generic_to_shared(s);
    asm volatile("cp.async.cg.shared.global [%0],[%1],16;" :: "r"(a), "l"(g));
}
__device__ __forceinline__ void cpcommit() { asm volatile("cp.async.commit_group;"); }
template<int N> __device__ __forceinline__ void cpwait() {
    asm volatile("cp.async.wait_group %0;" :: "n"(N));
}

// ---------------- prepass: round fp32 -> tf32 ------------------------------
template<int T>
__global__ void __launch_bounds__(256)
round_tf(const float* __restrict__ src, int n4)
{
    int i = blockIdx.x * 256 + threadIdx.x;
    if (i >= n4) return;
    float* dst = (T == 0) ? g_xr : g_wr[T - 1];
    float4 v = ((const float4*)src)[i];
    v.x = rtf(v.x); v.y = rtf(v.y); v.z = rtf(v.z); v.w = rtf(v.w);
    ((float4*)dst)[i] = v;
}

// ---------------- GEMM: C = A @ W^T + bias (tf32 tensor core) --------------
// DST 0/1/2 -> g_q/g_k/g_v scatter [B,H,P,D] (tf32-rounded, DST0 pre-scaled);
// DST 3     -> Cout [NTOK,EMB] fp32, A taken from g_ctx.
#define GP 36                      // smem row pitch (==4 mod 32: conflict-free frags)
#define GEMM_SMEM (2 * 128 * GP * 2)   // floats: 2 stages x (A + B)

template<int DST>
__global__ void __launch_bounds__(256, 2)
gemm_tc(const float* __restrict__ bias, float* __restrict__ Cout)
{
    extern __shared__ float sm[];
    float* As = sm;                       // [2][128][GP]
    float* Bs = sm + 2 * 128 * GP;        // [2][128][GP]

    const float* A = (DST == 3) ? (const float*)g_ctx : (const float*)g_xr;
    const float* W = g_wr[DST];

    const int tid = threadIdx.x;
    const int mBase = blockIdx.y * 128, nBase = blockIdx.x * 128;
    const float* Ag = A + (size_t)mBase * EMB;
    const float* Wg = W + (size_t)nBase * EMB;

    const int lr = tid >> 3, lq = tid & 7;

    auto load_tile = [&](int st, int kt) {
        float* Ad = As + st * 128 * GP;
        float* Bd = Bs + st * 128 * GP;
        const float* Asrc = Ag + kt * 32 + lq * 4;
        const float* Bsrc = Wg + kt * 32 + lq * 4;
        #pragma unroll
        for (int i = 0; i < 4; i++) {
            int row = lr + i * 32;
            cpa16(&Ad[row * GP + lq * 4], Asrc + (size_t)row * EMB);
            cpa16(&Bd[row * GP + lq * 4], Bsrc + (size_t)row * EMB);
        }
        cpcommit();
    };

    load_tile(0, 0);
    load_tile(1, 1);

    const int lane = tid & 31, warp = tid >> 5;
    const int wm = (warp >> 2) * 64, wn = (warp & 3) * 32;
    const int r = lane >> 2, cc = lane & 3;

    float acc[4][4][4];
    #pragma unroll
    for (int a = 0; a < 4; a++)
        #pragma unroll
        for (int b = 0; b < 4; b++)
            #pragma unroll
            for (int c = 0; c < 4; c++) acc[a][b][c] = 0.f;

    for (int kt = 0; kt < 32; kt++) {
        if (kt < 31) cpwait<1>(); else cpwait<0>();
        __syncthreads();
        const float* Ab = As + (kt & 1) * 128 * GP;
        const float* Bb = Bs + (kt & 1) * 128 * GP;

        #pragma unroll
        for (int ks = 0; ks < 4; ks++) {
            const int k0 = ks * 8;
            unsigned af[4][4], bf[4][2];
            #pragma unroll
            for (int mt = 0; mt < 4; mt++) {
                const float* p = Ab + (wm + mt * 16 + r) * GP + k0 + cc;
                af[mt][0] = __float_as_uint(p[0]);
                af[mt][1] = __float_as_uint(p[8 * GP]);
                af[mt][2] = __float_as_uint(p[4]);
                af[mt][3] = __float_as_uint(p[8 * GP + 4]);
            }
            #pragma unroll
            for (int nt = 0; nt < 4; nt++) {
                const float* p = Bb + (wn + nt * 8 + r) * GP + k0 + cc;
                bf[nt][0] = __float_as_uint(p[0]);
                bf[nt][1] = __float_as_uint(p[4]);
            }
            #pragma unroll
            for (int mt = 0; mt < 4; mt++)
                #pragma unroll
                for (int nt = 0; nt < 4; nt++)
                    mma8(acc[mt][nt], af[mt], bf[nt]);
        }
        __syncthreads();
        if (kt + 2 < 32) load_tile(kt & 1, kt + 2);
    }

    // epilogue
    #pragma unroll
    for (int mt = 0; mt < 4; mt++) {
        #pragma unroll
        for (int nt = 0; nt < 4; nt++) {
            int row = mBase + wm + mt * 16 + r;
            int col = nBase + wn + nt * 8 + cc * 2;
            float b0v = bias[col], b1v = bias[col + 1];
            float v0 = acc[mt][nt][0] + b0v, v1 = acc[mt][nt][1] + b1v;
            float v2 = acc[mt][nt][2] + b0v, v3 = acc[mt][nt][3] + b1v;
            if (DST < 3) {
                const float s = (DST == 0) ? 0.03125f : 1.0f;  // fold 1/sqrt(P)
                v0 = rtf(v0 * s); v1 = rtf(v1 * s);
                v2 = rtf(v2 * s); v3 = rtf(v3 * s);
                int b = row >> 10, p = row & 1023, h = col >> 6, d = col & 63;
                float* base = (DST == 0) ? g_q : (DST == 1) ? g_k : g_v;
                float* dst = base + (((size_t)(b * HEADS + h) * SEQ) + p) * HDIM + d;
                *(float2*)dst = make_float2(v0, v1);
                *(float2*)(dst + 8 * HDIM) = make_float2(v2, v3);   // row+8
            } else {
                float* dst = Cout + (size_t)row * EMB + col;
                *(float2*)dst = make_float2(v0, v1);
                *(float2*)(dst + 8 * EMB) = make_float2(v2, v3);
            }
        }
    }
}

// ---------------- flash attention, tf32 tensor core ------------------------
// BM=128 rows/block, BN=64 keys/iter, D=64. 8 warps x 16 rows.
// Q fragments register-resident; K/V cp.async double-buffered; P via smem
// (aliases the Q staging tile).
#define AP 68                      // smem row pitch
#define ATTN_SMEM (128 * AP + 2 * 64 * AP + 2 * 64 * AP)   // floats

__global__ void __launch_bounds__(256, 1)
attn_tc()
{
    extern __shared__ float sm[];
    float* Qs = sm;                        // [128][AP]   (aliased as Ps)
    float* Ks = sm + 128 * AP;             // [2][64][AP]
    float* Vs = Ks + 2 * 64 * AP;          // [2][64][AP]

    const int tid = threadIdx.x, lane = tid & 31, warp = tid >> 5;
    const int bh = blockIdx.y, qBase = blockIdx.x * 128;
    const int wm = warp * 16;
    const int r = lane >> 2, cc = lane & 3;

    const float* Qg = g_q + ((size_t)bh * SEQ + qBase) * HDIM;
    const float* Kg = g_k + (size_t)bh * SEQ * HDIM;
    const float* Vg = g_v + (size_t)bh * SEQ * HDIM;

    // stage Q, then pull loop-invariant A-fragments into registers
    #pragma unroll
    for (int i = 0; i < 8; i++) {
        int f = tid + i * 256;
        int row = f >> 4, q = f & 15;
        *(float4*)&Qs[row * AP + q * 4] = *(const float4*)&Qg[row * 64 + q * 4];
    }
    __syncthreads();

    unsigned qf[8][4];
    #pragma unroll
    for (int ks = 0; ks < 8; ks++) {
        const float* p = &Qs[(wm + r) * AP + ks * 8 + cc];
        qf[ks][0] = __float_as_uint(p[0]);
        qf[ks][1] = __float_as_uint(p[8 * AP]);
        qf[ks][2] = __float_as_uint(p[4]);
        qf[ks][3] = __float_as_uint(p[8 * AP + 4]);
    }
    __syncthreads();   // Ps may overwrite Qs from here on

    auto issue_kv = [&](int st, int t) {
        float* Kd = Ks + st * 64 * AP;
        float* Vd = Vs + st * 64 * AP;
        const float* Ksrc = Kg + (size_t)t * 64 * 64;
        const float* Vsrc = Vg + (size_t)t * 64 * 64;
        #pragma unroll
        for (int i = 0; i < 4; i++) {
            int f = tid + i * 256;
            int row = f >> 4, q = f & 15;
            cpa16(&Kd[row * AP + q * 4], Ksrc + row * 64 + q * 4);
            cpa16(&Vd[row * AP + q * 4], Vsrc + row * 64 + q * 4);
        }
        cpcommit();
    };
    issue_kv(0, 0);
    issue_kv(1, 1);

    const float NEG_INF = __int_as_float(0xff800000);
    float o[8][4];
    #pragma unroll
    for (int nt = 0; nt < 8; nt++)
        #pragma unroll
        for (int j = 0; j < 4; j++) o[nt][j] = 0.f;
    float m0 = NEG_INF, m1 = NEG_INF, l0 = 0.f, l1 = 0.f;

    for (int t = 0; t < 16; t++) {
        if (t < 15) cpwait<1>(); else cpwait<0>();
        __syncthreads();
        const float* Kb = Ks + (t & 1) * 64 * AP;
        const float* Vb = Vs + (t & 1) * 64 * AP;

        // S = Q K^T  (Q pre-scaled by 1/32)
        float s[8][4];
        #pragma unroll
        for (int nt = 0; nt < 8; nt++)
            #pragma unroll
            for (int j = 0; j < 4; j++) s[nt][j] = 0.f;

        #pragma unroll
        for (int ks = 0; ks < 8; ks++) {
            #pragma unroll
            for (int nt = 0; nt < 8; nt++) {
                unsigned bf[2];
                const float* p = &Kb[(nt * 8 + r) * AP + ks * 8 + cc];
                bf[0] = __float_as_uint(p[0]);
                bf[1] = __float_as_uint(p[4]);
                mma8(s[nt], qf[ks], bf);
            }
        }

        // online softmax (rows r and r+8; 4 lanes/row -> shfl 1,2)
        float mx0 = s[0][0], mx1 = s[0][2];
        #pragma unroll
        for (int nt = 0; nt < 8; nt++) {
            mx0 = fmaxf(mx0, fmaxf(s[nt][0], s[nt][1]));
            mx1 = fmaxf(mx1, fmaxf(s[nt][2], s[nt][3]));
        }
        mx0 = fmaxf(mx0, __shfl_xor_sync(0xffffffffu, mx0, 1));
        mx0 = fmaxf(mx0, __shfl_xor_sync(0xffffffffu, mx0, 2));
        mx1 = fmaxf(mx1, __shfl_xor_sync(0xffffffffu, mx1, 1));
        mx1 = fmaxf(mx1, __shfl_xor_sync(0xffffffffu, mx1, 2));
        float mn0 = fmaxf(m0, mx0), mn1 = fmaxf(m1, mx1);
        float a0 = __expf(m0 - mn0), a1 = __expf(m1 - mn1);
        float rs0 = 0.f, rs1 = 0.f;
        #pragma unroll
        for (int nt = 0; nt < 8; nt++) {
            s[nt][0] = __expf(s[nt][0] - mn0);
            s[nt][1] = __expf(s[nt][1] - mn0);
            s[nt][2] = __expf(s[nt][2] - mn1);
            s[nt][3] = __expf(s[nt][3] - mn1);
            rs0 += s[nt][0] + s[nt][1];
            rs1 += s[nt][2] + s[nt][3];
            o[nt][0] *= a0; o[nt][1] *= a0;
            o[nt][2] *= a1; o[nt][3] *= a1;
        }
        rs0 += __shfl_xor_sync(0xffffffffu, rs0, 1);
        rs0 += __shfl_xor_sync(0xffffffffu, rs0, 2);
        rs1 += __shfl_xor_sync(0xffffffffu, rs1, 1);
        rs1 += __shfl_xor_sync(0xffffffffu, rs1, 2);
        l0 = l0 * a0 + rs0; l1 = l1 * a1 + rs1;
        m0 = mn0; m1 = mn1;

        // P -> smem (tf32-rounded); per-warp private rows
        float* Ps = Qs;
        #pragma unroll
        for (int nt = 0; nt < 8; nt++) {
            *(float2*)&Ps[(wm + r) * AP + nt * 8 + cc * 2] =
                make_float2(rtf(s[nt][0]), rtf(s[nt][1]));
            *(float2*)&Ps[(wm + r + 8) * AP + nt * 8 + cc * 2] =
                make_float2(rtf(s[nt][2]), rtf(s[nt][3]));
        }
        __syncwarp();

        // O += P V
        #pragma unroll
        for (int ks = 0; ks < 8; ks++) {
            unsigned af[4];
            const float* p = &Ps[(wm + r) * AP + ks * 8 + cc];
            af[0] = __float_as_uint(p[0]);
            af[1] = __float_as_uint(p[8 * AP]);
            af[2] = __float_as_uint(p[4]);
            af[3] = __float_as_uint(p[8 * AP + 4]);
            #pragma unroll
            for (int nt = 0; nt < 8; nt++) {
                unsigned bf[2];
                const float* q = &Vb[(ks * 8 + cc) * AP + nt * 8 + r];
                bf[0] = __float_as_uint(q[0]);
                bf[1] = __float_as_uint(q[4 * AP]);
                mma8(o[nt], af, bf);
            }
        }
        __syncthreads();
        if (t + 2 < 16) issue_kv(t & 1, t + 2);
    }

    // normalize, round to tf32, write ctx [B,P,E]
    float inv0 = 1.f / l0, inv1 = 1.f / l1;
    int b = bh >> 4, h = bh & 15;
    int p0 = qBase + wm + r;
    float* d0 = g_ctx + ((size_t)(b * SEQ + p0)) * EMB + h * HDIM;
    float* d1 = g_ctx + ((size_t)(b * SEQ + p0 + 8)) * EMB + h * HDIM;
    #pragma unroll
    for (int nt = 0; nt < 8; nt++) {
        int col = nt * 8 + cc * 2;
        *(float2*)&d0[col] = make_float2(rtf(o[nt][0] * inv0), rtf(o[nt][1] * inv0));
        *(float2*)&d1[col] = make_float2(rtf(o[nt][2] * inv1), rtf(o[nt][3] * inv1));
    }
}

// ---------------------------------------------------------------------------
extern "C" void kernel_launch(void* const* d_in, const int* in_sizes, int n_in,
                              void* d_out, int out_size)
{
    const float* x  = (const float*)d_in[0];
    const float* wq = (const float*)d_in[1];
    const float* bq = (const float*)d_in[2];
    const float* wk = (const float*)d_in[3];
    const float* bk = (const float*)d_in[4];
    const float* wv = (const float*)d_in[5];
    const float* bv = (const float*)d_in[6];
    const float* wo = (const float*)d_in[7];
    const float* bo = (const float*)d_in[8];
    float* out = (float*)d_out;

    const int nx4 = NTOK * EMB / 4, nw4 = EMB * EMB / 4;
    round_tf<0><<<(nx4 + 255) / 256, 256>>>(x,  nx4);
    round_tf<1><<<(nw4 + 255) / 256, 256>>>(wq, nw4);
    round_tf<2><<<(nw4 + 255) / 256, 256>>>(wk, nw4);
    round_tf<3><<<(nw4 + 255) / 256, 256>>>(wv, nw4);
    round_tf<4><<<(nw4 + 255) / 256, 256>>>(wo, nw4);

    const int gsmem = GEMM_SMEM * (int)sizeof(float);
    cudaFuncSetAttribute(gemm_tc<0>, cudaFuncAttributeMaxDynamicSharedMemorySize, gsmem);
    cudaFuncSetAttribute(gemm_tc<1>, cudaFuncAttributeMaxDynamicSharedMemorySize, gsmem);
    cudaFuncSetAttribute(gemm_tc<2>, cudaFuncAttributeMaxDynamicSharedMemorySize, gsmem);
    cudaFuncSetAttribute(gemm_tc<3>, cudaFuncAttributeMaxDynamicSharedMemorySize, gsmem);

    dim3 ggrid(EMB / 128, NTOK / 128);
    gemm_tc<0><<<ggrid, 256, gsmem>>>(bq, nullptr);
    gemm_tc<1><<<ggrid, 256, gsmem>>>(bk, nullptr);
    gemm_tc<2><<<ggrid, 256, gsmem>>>(bv, nullptr);

    const int asmem = ATTN_SMEM * (int)sizeof(float);
    cudaFuncSetAttribute(attn_tc, cudaFuncAttributeMaxDynamicSharedMemorySize, asmem);
    attn_tc<<<dim3(SEQ / 128, BATCH * HEADS), 256, asmem>>>();

    gemm_tc<3><<<ggrid, 256, gsmem>>>(bo, out);

    (void)in_sizes; (void)n_in; (void)out_size;
}